// round 3
// baseline (speedup 1.0000x reference)
#include <cuda_runtime.h>
#include <cuda_bf16.h>
#include <cstdint>

#define NUM_EMBED 8192
#define ED 64
#define NTOK 32768
#define CH_STRIDE 4096
#define B_STRIDE 262144

#define OFF_LOSS 2097152
#define OFF_IDX  2097153
#define OFF_BIN  (2097153 + 32768)

#define KP 192                 /* split-bf16 K' */
#define ROW_BYTES 384          /* packed row: 192 bf16 */
#define MCTA 256               /* tokens per CTA */
#define NT 64                  /* codes per tile */
#define NTILES (NUM_EMBED / NT)      /* 128 */
#define NCTA (NTOK / MCTA)           /* 128 */

#define ROWB 400               /* padded smem row stride (conflict-free ldmatrix) */
#define SMA 0
#define SMA_BYTES (MCTA * ROWB)          /* 102400 */
#define SMB_BYTES (NT * ROWB)            /* 25600 */
#define SMB0 SMA_BYTES
#define SMB1 (SMB0 + SMB_BYTES)
#define SMTOT (SMB1 + SMB_BYTES)         /* 153600 */

#define GAP_EPS 4e-4f

__device__ __align__(16) unsigned char g_Aimg[(size_t)NTOK * ROW_BYTES];
__device__ __align__(16) unsigned char g_Bimg[(size_t)NUM_EMBED * ROW_BYTES];
__device__ float g_cnorm[NUM_EMBED * ED];
__device__ int   g_idx[NTOK];
__device__ int   g_amb[NTOK];
__device__ int   g_namb;
__device__ float g_partial[128];

// ===================== PTX helpers (baseline PTX only, no 'a' features) =====================
__device__ __forceinline__ uint32_t smem_u32(const void* p) {
    uint32_t a;
    asm("{ .reg .u64 t; cvta.to.shared.u64 t, %1; cvt.u32.u64 %0, t; }" : "=r"(a) : "l"(p));
    return a;
}
__device__ __forceinline__ void ldsm_x4(uint32_t* r, uint32_t addr) {
    asm volatile("ldmatrix.sync.aligned.m8n8.x4.shared.b16 {%0,%1,%2,%3}, [%4];"
        : "=r"(r[0]), "=r"(r[1]), "=r"(r[2]), "=r"(r[3]) : "r"(addr));
}
__device__ __forceinline__ void mma_bf16(float* d, const uint32_t* a, uint32_t b0, uint32_t b1) {
    asm volatile("mma.sync.aligned.m16n8k16.row.col.f32.bf16.bf16.f32 "
        "{%0,%1,%2,%3}, {%4,%5,%6,%7}, {%8,%9}, {%0,%1,%2,%3};"
        : "+f"(d[0]), "+f"(d[1]), "+f"(d[2]), "+f"(d[3])
        : "r"(a[0]), "r"(a[1]), "r"(a[2]), "r"(a[3]), "r"(b0), "r"(b1));
}
#define CP_ASYNC16(dst, src) asm volatile("cp.async.cg.shared.global [%0], [%1], 16;" :: "r"(dst), "l"(src))
#define CP_COMMIT()          asm volatile("cp.async.commit_group;" ::: "memory")
#define CP_WAIT0()           asm volatile("cp.async.wait_group 0;" ::: "memory")
#define CP_WAIT1()           asm volatile("cp.async.wait_group 1;" ::: "memory")

// ===================== preprocessing: normalize + split-bf16 pack =====================
__global__ void k_prep_c(const float* __restrict__ ew) {
    int k = blockIdx.x * 128 + threadIdx.x;
    if (k == 0 && blockIdx.x == 0) g_namb = 0;
    float v[64]; float ss = 0.f;
#pragma unroll
    for (int i = 0; i < 16; ++i) {
        float4 q = ((const float4*)(ew + (size_t)k * ED))[i];
        v[4*i+0] = q.x; v[4*i+1] = q.y; v[4*i+2] = q.z; v[4*i+3] = q.w;
        ss = fmaf(q.x, q.x, ss); ss = fmaf(q.y, q.y, ss);
        ss = fmaf(q.z, q.z, ss); ss = fmaf(q.w, q.w, ss);
    }
    float nm = fmaxf(__fsqrt_rn(ss), 1e-12f);
    unsigned short hs[64], ls[64];
#pragma unroll
    for (int c = 0; c < 64; ++c) {
        float x = __fdiv_rn(v[c], nm);
        g_cnorm[(size_t)k * ED + c] = x;
        __nv_bfloat16 h = __float2bfloat16(x);
        __nv_bfloat16 l = __float2bfloat16(x - __bfloat162float(h));
        hs[c] = __bfloat16_as_ushort(h);
        ls[c] = __bfloat16_as_ushort(l);
    }
    unsigned char* base = g_Bimg + (size_t)k * ROW_BYTES;
#pragma unroll
    for (int blk = 0; blk < 8; ++blk) {
        uint4 ph, pl;
        ph.x = hs[blk*8+0] | ((uint32_t)hs[blk*8+1] << 16);
        ph.y = hs[blk*8+2] | ((uint32_t)hs[blk*8+3] << 16);
        ph.z = hs[blk*8+4] | ((uint32_t)hs[blk*8+5] << 16);
        ph.w = hs[blk*8+6] | ((uint32_t)hs[blk*8+7] << 16);
        pl.x = ls[blk*8+0] | ((uint32_t)ls[blk*8+1] << 16);
        pl.y = ls[blk*8+2] | ((uint32_t)ls[blk*8+3] << 16);
        pl.z = ls[blk*8+4] | ((uint32_t)ls[blk*8+5] << 16);
        pl.w = ls[blk*8+6] | ((uint32_t)ls[blk*8+7] << 16);
        // B' = [bh | bl | bh]
        *(uint4*)(base + blk * 16)       = ph;
        *(uint4*)(base + 128 + blk * 16) = pl;
        *(uint4*)(base + 256 + blk * 16) = ph;
    }
}

__global__ void k_prep_z(const float* __restrict__ z) {
    int t = blockIdx.x * 128 + threadIdx.x;
    int b = t >> 12, p = t & 4095;
    const float* zb = z + (size_t)b * B_STRIDE + p;
    float v[64]; float ss = 0.f;
#pragma unroll
    for (int c = 0; c < 64; ++c) { v[c] = zb[c * CH_STRIDE]; ss = fmaf(v[c], v[c], ss); }
    float nm = fmaxf(__fsqrt_rn(ss), 1e-12f);
    unsigned short hs[64], ls[64];
#pragma unroll
    for (int c = 0; c < 64; ++c) {
        float x = __fdiv_rn(v[c], nm);
        __nv_bfloat16 h = __float2bfloat16(x);
        __nv_bfloat16 l = __float2bfloat16(x - __bfloat162float(h));
        hs[c] = __bfloat16_as_ushort(h);
        ls[c] = __bfloat16_as_ushort(l);
    }
    unsigned char* base = g_Aimg + (size_t)t * ROW_BYTES;
#pragma unroll
    for (int blk = 0; blk < 8; ++blk) {
        uint4 ph, pl;
        ph.x = hs[blk*8+0] | ((uint32_t)hs[blk*8+1] << 16);
        ph.y = hs[blk*8+2] | ((uint32_t)hs[blk*8+3] << 16);
        ph.z = hs[blk*8+4] | ((uint32_t)hs[blk*8+5] << 16);
        ph.w = hs[blk*8+6] | ((uint32_t)hs[blk*8+7] << 16);
        pl.x = ls[blk*8+0] | ((uint32_t)ls[blk*8+1] << 16);
        pl.y = ls[blk*8+2] | ((uint32_t)ls[blk*8+3] << 16);
        pl.z = ls[blk*8+4] | ((uint32_t)ls[blk*8+5] << 16);
        pl.w = ls[blk*8+6] | ((uint32_t)ls[blk*8+7] << 16);
        // A' = [ah | ah | al]
        *(uint4*)(base + blk * 16)       = ph;
        *(uint4*)(base + 128 + blk * 16) = ph;
        *(uint4*)(base + 256 + blk * 16) = pl;
    }
}

// ===================== main mma.sync GEMM + argmax =====================
// CTA: 256 tokens, 8 warps; warp w owns token rows [w*32, w*32+32), all 64 codes of a tile.
__global__ __launch_bounds__(256, 1) void k_gemm_argmax() {
    extern __shared__ char smem[];
    uint32_t sbase = smem_u32(smem);
    const int tid = threadIdx.x, wid = tid >> 5, lane = tid & 31;

    // prologue: A (whole CTA, 256 rows) + B tile 0 -> group 0
    const unsigned char* Ag = g_Aimg + (size_t)blockIdx.x * MCTA * ROW_BYTES;
    for (int i = tid; i < MCTA * 24; i += 256) {
        int row = i / 24, c = i % 24;
        CP_ASYNC16(sbase + SMA + row * ROWB + c * 16, Ag + (size_t)row * ROW_BYTES + c * 16);
    }
    for (int i = tid; i < NT * 24; i += 256) {
        int row = i / 24, c = i % 24;
        CP_ASYNC16(sbase + SMB0 + row * ROWB + c * 16, g_Bimg + (size_t)row * ROW_BYTES + c * 16);
    }
    CP_COMMIT();

    // per-lane ldmatrix base offsets (group g = lane>>3):
    // row_in_16 = ((g&1)<<3) + (lane&7), kcol = (g>>1)<<3
    const int lg = lane >> 3;
    const int lrow = ((lg & 1) << 3) + (lane & 7);
    const int lkc  = (lg >> 1) << 3;
    const int mrow0 = wid * 32;
    uint32_t aaddr0 = sbase + SMA + (uint32_t)(mrow0 + 0  + lrow) * ROWB + lkc * 2;
    uint32_t aaddr1 = sbase + SMA + (uint32_t)(mrow0 + 16 + lrow) * ROWB + lkc * 2;
    uint32_t brel0 = (uint32_t)(0  + lrow) * ROWB + lkc * 2;
    uint32_t brel1 = (uint32_t)(16 + lrow) * ROWB + lkc * 2;
    uint32_t brel2 = (uint32_t)(32 + lrow) * ROWB + lkc * 2;
    uint32_t brel3 = (uint32_t)(48 + lrow) * ROWB + lkc * 2;

    float best[4] = {-1e30f, -1e30f, -1e30f, -1e30f};
    float sec[4]  = {-1e30f, -1e30f, -1e30f, -1e30f};
    int   bidx[4] = {0, 0, 0, 0};

    const int kcol0 = (lane & 3) << 1;

    for (int nt = 0; nt < NTILES; ++nt) {
        // prefetch next B tile into the other buffer
        if (nt + 1 < NTILES) {
            uint32_t dstb = sbase + (((nt + 1) & 1) ? SMB1 : SMB0);
            const unsigned char* src = g_Bimg + (size_t)(nt + 1) * NT * ROW_BYTES;
            for (int i = tid; i < NT * 24; i += 256) {
                int row = i / 24, c = i % 24;
                CP_ASYNC16(dstb + row * ROWB + c * 16, src + (size_t)row * ROW_BYTES + c * 16);
            }
            CP_COMMIT();
            CP_WAIT1();
        } else {
            CP_WAIT0();
        }
        __syncthreads();

        uint32_t bbuf = sbase + ((nt & 1) ? SMB1 : SMB0);

        float acc[2][8][4];
#pragma unroll
        for (int mf = 0; mf < 2; ++mf)
#pragma unroll
            for (int nf = 0; nf < 8; ++nf)
#pragma unroll
                for (int r = 0; r < 4; ++r) acc[mf][nf][r] = 0.f;

#pragma unroll
        for (int ks = 0; ks < 12; ++ks) {
            uint32_t a0[4], a1[4], bf0[4], bf1[4], bf2[4], bf3[4];
            ldsm_x4(a0, aaddr0 + ks * 32);
            ldsm_x4(a1, aaddr1 + ks * 32);
            ldsm_x4(bf0, bbuf + brel0 + ks * 32);
            ldsm_x4(bf1, bbuf + brel1 + ks * 32);
            ldsm_x4(bf2, bbuf + brel2 + ks * 32);
            ldsm_x4(bf3, bbuf + brel3 + ks * 32);
            // bfq = {b0 of nf=2q, b0 of nf=2q+1, b1 of nf=2q, b1 of nf=2q+1}
            mma_bf16(acc[0][0], a0, bf0[0], bf0[2]);
            mma_bf16(acc[1][0], a1, bf0[0], bf0[2]);
            mma_bf16(acc[0][1], a0, bf0[1], bf0[3]);
            mma_bf16(acc[1][1], a1, bf0[1], bf0[3]);
            mma_bf16(acc[0][2], a0, bf1[0], bf1[2]);
            mma_bf16(acc[1][2], a1, bf1[0], bf1[2]);
            mma_bf16(acc[0][3], a0, bf1[1], bf1[3]);
            mma_bf16(acc[1][3], a1, bf1[1], bf1[3]);
            mma_bf16(acc[0][4], a0, bf2[0], bf2[2]);
            mma_bf16(acc[1][4], a1, bf2[0], bf2[2]);
            mma_bf16(acc[0][5], a0, bf2[1], bf2[3]);
            mma_bf16(acc[1][5], a1, bf2[1], bf2[3]);
            mma_bf16(acc[0][6], a0, bf3[0], bf3[2]);
            mma_bf16(acc[1][6], a1, bf3[0], bf3[2]);
            mma_bf16(acc[0][7], a0, bf3[1], bf3[3]);
            mma_bf16(acc[1][7], a1, bf3[1], bf3[3]);
        }

        // argmax epilogue (codes ascending within tile: nf asc, then col 0/1)
        int kbase = nt * NT + kcol0;
#pragma unroll
        for (int mf = 0; mf < 2; ++mf) {
#pragma unroll
            for (int h = 0; h < 2; ++h) {
                int rs = mf * 2 + h;
#pragma unroll
                for (int nf = 0; nf < 8; ++nf) {
                    int kk = kbase + nf * 8;
                    float v0 = acc[mf][nf][h * 2 + 0];
                    float v1 = acc[mf][nf][h * 2 + 1];
                    float ob = best[rs];
                    sec[rs] = fmaxf(sec[rs], fminf(ob, v0));
                    best[rs] = fmaxf(ob, v0);
                    if (v0 > ob) bidx[rs] = kk;
                    float ob1 = best[rs];
                    sec[rs] = fmaxf(sec[rs], fminf(ob1, v1));
                    best[rs] = fmaxf(ob1, v1);
                    if (v1 > ob1) bidx[rs] = kk + 1;
                }
            }
        }
        __syncthreads();
    }

    // merge across the 4 lanes of each quad (they share token rows)
#pragma unroll
    for (int rs = 0; rs < 4; ++rs) {
        float b = best[rs], s = sec[rs];
        int i = bidx[rs];
#pragma unroll
        for (int off = 1; off <= 2; off <<= 1) {
            float b2 = __shfl_xor_sync(0xffffffffu, b, off);
            float s2 = __shfl_xor_sync(0xffffffffu, s, off);
            int   i2 = __shfl_xor_sync(0xffffffffu, i, off);
            s = fmaxf(fmaxf(s, s2), fminf(b, b2));
            if (b2 > b || (b2 == b && i2 < i)) { b = b2; i = i2; }
        }
        if ((lane & 3) == 0) {
            int mf = rs >> 1, h = rs & 1;
            int t = blockIdx.x * MCTA + mrow0 + mf * 16 + h * 8 + (lane >> 2);
            g_idx[t] = i;
            if (b - s < GAP_EPS) {
                int pos = atomicAdd(&g_namb, 1);
                g_amb[pos] = t;
            }
        }
    }
}

// ===================== exact fp32 fallback for ambiguous tokens =====================
__global__ void k_fallback(const float* __restrict__ z) {
    __shared__ float zs[64];
    __shared__ float nmS;
    __shared__ float rv[256];
    __shared__ int   ri[256];
    int tid = threadIdx.x;
    int n = g_namb;
    for (int it = blockIdx.x; it < n; it += gridDim.x) {
        int t = g_amb[it];
        int b = t >> 12, p = t & 4095;
        if (tid < 64) zs[tid] = z[(size_t)b * B_STRIDE + tid * CH_STRIDE + p];
        __syncthreads();
        if (tid == 0) {
            float ss = 0.f;
            for (int c = 0; c < 64; ++c) ss = fmaf(zs[c], zs[c], ss);
            nmS = fmaxf(__fsqrt_rn(ss), 1e-12f);
        }
        __syncthreads();
        if (tid < 64) zs[tid] = __fdiv_rn(zs[tid], nmS);
        __syncthreads();
        float bv = -1e30f; int bi = 0;
        for (int k = tid; k < NUM_EMBED; k += 256) {
            const float* cr = g_cnorm + (size_t)k * ED;
            float d = 0.f;
#pragma unroll 16
            for (int c = 0; c < 64; ++c) d = fmaf(zs[c], cr[c], d);
            if (d > bv) { bv = d; bi = k; }
        }
        rv[tid] = bv; ri[tid] = bi;
        __syncthreads();
        for (int s = 128; s > 0; s >>= 1) {
            if (tid < s) {
                if (rv[tid + s] > rv[tid] ||
                    (rv[tid + s] == rv[tid] && ri[tid + s] < ri[tid])) {
                    rv[tid] = rv[tid + s]; ri[tid] = ri[tid + s];
                }
            }
            __syncthreads();
        }
        if (tid == 0) g_idx[t] = ri[0];
        __syncthreads();
    }
}

// ===================== gather / STE / loss / idx / bincount =====================
__global__ void k3_zq_loss(const float* __restrict__ z, const float* __restrict__ ew,
                           float* __restrict__ out_zq, float* __restrict__ out_idx,
                           float* __restrict__ out_bin) {
    int tg = blockIdx.x * 256 + threadIdx.x;
    int b = tg >> 12, p = tg & 4095;
    const float* zb = z + (size_t)b * B_STRIDE + p;
    float* ob = out_zq + (size_t)b * B_STRIDE + p;
    int idx = g_idx[tg];
    out_idx[tg] = (float)idx;
    atomicAdd(&out_bin[idx], 1.0f);
    const float* w = ew + (size_t)idx * ED;
    float ss = 0.f;
#pragma unroll 8
    for (int c = 0; c < 64; ++c) {
        float zq = w[c];
        float zc = zb[c * CH_STRIDE];
        float d  = zq - zc;
        ob[c * CH_STRIDE] = zc + d;
        ss = fmaf(d, d, ss);
    }
    __shared__ float red[256];
    red[threadIdx.x] = ss;
    __syncthreads();
    for (int s = 128; s > 0; s >>= 1) {
        if (threadIdx.x < s) red[threadIdx.x] += red[threadIdx.x + s];
        __syncthreads();
    }
    if (threadIdx.x == 0) g_partial[blockIdx.x] = red[0];
}

__global__ void k4_loss(float* __restrict__ out_loss) {
    if (threadIdx.x == 0) {
        float s = 0.f;
        for (int i = 0; i < 128; ++i) s += g_partial[i];
        float m = s / 2097152.0f;
        out_loss[0] = 0.25f * m + m;
    }
}

extern "C" void kernel_launch(void* const* d_in, const int* in_sizes, int n_in,
                              void* d_out, int out_size) {
    const float* z  = (const float*)d_in[0];
    const float* ew = (const float*)d_in[1];
    float* out      = (float*)d_out;

    float* out_zq   = out;
    float* out_loss = out + OFF_LOSS;
    float* out_idx  = out + OFF_IDX;
    float* out_bin  = out + OFF_BIN;

    cudaMemsetAsync(out_bin, 0, NUM_EMBED * sizeof(float));

    k_prep_c<<<NUM_EMBED / 128, 128>>>(ew);
    k_prep_z<<<NTOK / 128, 128>>>(z);

    cudaFuncSetAttribute(k_gemm_argmax, cudaFuncAttributeMaxDynamicSharedMemorySize, SMTOT);
    k_gemm_argmax<<<NCTA, 256, SMTOT>>>();

    k_fallback<<<128, 256>>>(z);

    k3_zq_loss<<<NTOK / 256, 256>>>(z, ew, out_zq, out_idx, out_bin);
    k4_loss<<<1, 32>>>(out_loss);
}

// round 4
// speedup vs baseline: 1.6705x; 1.6705x over previous
#include <cuda_runtime.h>
#include <cstdint>

#define NUM_EMBED 8192
#define ED 64
#define NTOK 32768
#define CH_STRIDE 4096
#define B_STRIDE 262144

#define OFF_LOSS 2097152
#define OFF_IDX  2097153
#define OFF_BIN  (2097153 + 32768)

#define MCTA 32                      /* tokens per CTA */
#define NBLK (NTOK / MCTA)           /* 1024 */
#define KB 128                       /* codes per tile */
#define NTILES (NUM_EMBED / KB)      /* 64 */

__device__ float g_cnormT[ED * NUM_EMBED];  // [c][k] normalized codebook, transposed
__device__ float g_partial[NBLK];

typedef unsigned long long ull;

__device__ __forceinline__ void ffma2(ull &d, ull a, ull b) {
    asm("fma.rn.f32x2 %0, %1, %2, %0;" : "+l"(d) : "l"(a), "l"(b));
}
__device__ __forceinline__ float lo32(ull v) { return __uint_as_float((unsigned)(v & 0xFFFFFFFFULL)); }
__device__ __forceinline__ float hi32(ull v) { return __uint_as_float((unsigned)(v >> 32)); }
__device__ __forceinline__ uint32_t smem_u32(const void* p) {
    uint32_t a;
    asm("{ .reg .u64 t; cvta.to.shared.u64 t, %1; cvt.u32.u64 %0, t; }" : "=r"(a) : "l"(p));
    return a;
}
#define CP_ASYNC16(dst, src) asm volatile("cp.async.cg.shared.global [%0], [%1], 16;" :: "r"(dst), "l"(src))
#define CP_COMMIT()          asm volatile("cp.async.commit_group;" ::: "memory")
#define CP_WAIT0()           asm volatile("cp.async.wait_group 0;" ::: "memory")

// ---------------- K1: normalize codebook, store transposed [c][k] ----------------
__global__ void k1_normalize(const float* __restrict__ ew) {
    int k = blockIdx.x * blockDim.x + threadIdx.x;
    const float4* row = (const float4*)(ew + (size_t)k * ED);
    float4 v[16];
    float ss = 0.f;
#pragma unroll
    for (int i = 0; i < 16; ++i) {
        v[i] = row[i];
        ss = fmaf(v[i].x, v[i].x, ss);
        ss = fmaf(v[i].y, v[i].y, ss);
        ss = fmaf(v[i].z, v[i].z, ss);
        ss = fmaf(v[i].w, v[i].w, ss);
    }
    float dn = fmaxf(__fsqrt_rn(ss), 1e-12f);
#pragma unroll
    for (int i = 0; i < 16; ++i) {
        g_cnormT[(4 * i + 0) * NUM_EMBED + k] = __fdiv_rn(v[i].x, dn);
        g_cnormT[(4 * i + 1) * NUM_EMBED + k] = __fdiv_rn(v[i].y, dn);
        g_cnormT[(4 * i + 2) * NUM_EMBED + k] = __fdiv_rn(v[i].z, dn);
        g_cnormT[(4 * i + 3) * NUM_EMBED + k] = __fdiv_rn(v[i].w, dn);
    }
}

// ---------------- K2: fused normalize + GEMM-argmax + gather/STE/loss/idx/bin ----------------
// CTA: 32 tokens, 128 threads (4 warps); warp owns 8 tokens, lane owns 4 codes/tile.
// smem layout (bytes):
#define SM_ZRAW 0                    /* 64*32*4   = 8192  raw z [c][t] */
#define SM_ZS2  8192                 /* 64*32*8   = 16384 normalized dup f32x2 [c][t] */
#define SM_NM   24576                /* 32*4 */
#define SM_IDXS 24704                /* 32*4 */
#define SM_RED  24832                /* 128*4 */
#define SM_WS0  25344                /* 64*128*4  = 32768 */
#define SM_WS1  (SM_WS0 + 32768)
#define SM_TOT  (SM_WS1 + 32768)     /* 90880 */

__global__ __launch_bounds__(128, 2) void k2_all(const float* __restrict__ z,
                                                 const float* __restrict__ ew,
                                                 float* __restrict__ out_zq,
                                                 float* __restrict__ out_idx,
                                                 float* __restrict__ out_bin) {
    extern __shared__ char sm_[];
    uint32_t sbase = smem_u32(sm_);
    float*  zraw = (float*)(sm_ + SM_ZRAW);
    float2* zs2  = (float2*)(sm_ + SM_ZS2);
    float*  nm   = (float*)(sm_ + SM_NM);
    int*    idxs = (int*)(sm_ + SM_IDXS);
    float*  red  = (float*)(sm_ + SM_RED);

    const int tid  = threadIdx.x;
    const int warp = tid >> 5;
    const int lane = tid & 31;

    const int tok0 = blockIdx.x * MCTA;
    const int b    = tok0 >> 12;
    const int p0   = tok0 & 4095;
    const float* zb = z + (size_t)b * B_STRIDE + p0;

    // prefetch codebook tile 0 first (overlaps z setup)
    for (int i = tid; i < 2048; i += 128) {
        int c = i >> 5, q = i & 31;
        CP_ASYNC16(sbase + SM_WS0 + (c * KB + q * 4) * 4,
                   (const char*)(g_cnormT + (size_t)c * NUM_EMBED) + q * 16);
    }
    CP_COMMIT();

    // load raw z tile [c][32]
    for (int i = tid; i < 512; i += 128) {
        int c = i >> 3, q = i & 7;
        float4 v = ((const float4*)(zb + c * CH_STRIDE))[q];
        ((float4*)(zraw + c * 32))[q] = v;
    }
    __syncthreads();

    // per-token norms (same op order as the passing R1 kernel)
    if (tid < 32) {
        float ss = 0.f;
        for (int c = 0; c < 64; ++c) {
            float x = zraw[c * 32 + tid];
            ss = fmaf(x, x, ss);
        }
        nm[tid] = fmaxf(__fsqrt_rn(ss), 1e-12f);
    }
    __syncthreads();

    // normalized duplicated z
    for (int i = tid; i < 64 * 32; i += 128) {
        int t = i & 31;
        float x = __fdiv_rn(zraw[i], nm[t]);
        zs2[i] = make_float2(x, x);
    }

    float best[8];
    int   bidx[8];
#pragma unroll
    for (int t = 0; t < 8; ++t) { best[t] = -1e30f; bidx[t] = 0; }

    const int t0 = warp * 8;

    for (int nt = 0; nt < NTILES; ++nt) {
        CP_WAIT0();
        __syncthreads();

        uint32_t wsC = (nt & 1) ? (sbase + SM_WS1) : (sbase + SM_WS0);
        const float* ws = (nt & 1) ? (float*)(sm_ + SM_WS1) : (float*)(sm_ + SM_WS0);

        // prefetch next tile into the other buffer (safe: sync above)
        if (nt + 1 < NTILES) {
            uint32_t wsN = (nt & 1) ? (sbase + SM_WS0) : (sbase + SM_WS1);
            const char* src0 = (const char*)(g_cnormT + (size_t)(nt + 1) * KB);
            for (int i = tid; i < 2048; i += 128) {
                int c = i >> 5, q = i & 31;
                CP_ASYNC16(wsN + (c * KB + q * 4) * 4,
                           src0 + (size_t)c * NUM_EMBED * 4 + q * 16);
            }
            CP_COMMIT();
        }

        ull acc[8][2];
#pragma unroll
        for (int t = 0; t < 8; ++t) { acc[t][0] = 0ULL; acc[t][1] = 0ULL; }

#pragma unroll 8
        for (int c = 0; c < 64; ++c) {
            const ull* zp = (const ull*)zs2 + (c << 5) + t0;
            ulonglong2 a0 = *(const ulonglong2*)(zp + 0);
            ulonglong2 a1 = *(const ulonglong2*)(zp + 2);
            ulonglong2 a2 = *(const ulonglong2*)(zp + 4);
            ulonglong2 a3 = *(const ulonglong2*)(zp + 6);
            ulonglong2 bb = *(const ulonglong2*)(ws + c * KB + (lane << 2));
            ull aa[8] = {a0.x, a0.y, a1.x, a1.y, a2.x, a2.y, a3.x, a3.y};
#pragma unroll
            for (int t = 0; t < 8; ++t) {
                ffma2(acc[t][0], aa[t], bb.x);
                ffma2(acc[t][1], aa[t], bb.y);
            }
        }

        // running argmax update, codes ascending (strict > => first-index-wins)
        int kb = nt * KB + (lane << 2);
#pragma unroll
        for (int t = 0; t < 8; ++t) {
            float v0 = lo32(acc[t][0]);
            float v1 = hi32(acc[t][0]);
            float v2 = lo32(acc[t][1]);
            float v3 = hi32(acc[t][1]);
            if (v0 > best[t]) { best[t] = v0; bidx[t] = kb; }
            if (v1 > best[t]) { best[t] = v1; bidx[t] = kb + 1; }
            if (v2 > best[t]) { best[t] = v2; bidx[t] = kb + 2; }
            if (v3 > best[t]) { best[t] = v3; bidx[t] = kb + 3; }
        }
    }

    // lane merge: lexicographic max on (val, -idx)
#pragma unroll
    for (int t = 0; t < 8; ++t) {
        float v = best[t];
        int   i = bidx[t];
#pragma unroll
        for (int off = 16; off > 0; off >>= 1) {
            float v2 = __shfl_xor_sync(0xffffffffu, v, off);
            int   i2 = __shfl_xor_sync(0xffffffffu, i, off);
            if (v2 > v || (v2 == v && i2 < i)) { v = v2; i = i2; }
        }
        if (lane == 0) idxs[t0 + t] = i;
    }
    __syncthreads();

    // ---- fused epilogue: gather, STE output, loss partial, idx, bincount ----
    // lane = token (0..31), warp owns channels [warp*16, warp*16+16)
    int myidx = idxs[lane];
    const float4* er = (const float4*)(ew + (size_t)myidx * ED + warp * 16);
    float4 e0 = er[0], e1 = er[1], e2 = er[2], e3 = er[3];
    float vals[16] = {e0.x, e0.y, e0.z, e0.w, e1.x, e1.y, e1.z, e1.w,
                      e2.x, e2.y, e2.z, e2.w, e3.x, e3.y, e3.z, e3.w};
    float ssq = 0.f;
#pragma unroll
    for (int j = 0; j < 16; ++j) {
        int ch = warp * 16 + j;
        float zc = zraw[ch * 32 + lane];
        float d  = vals[j] - zc;
        out_zq[(size_t)(b * 64 + ch) * 4096 + p0 + lane] = zc + d;
        ssq = fmaf(d, d, ssq);
    }
    red[tid] = ssq;
    __syncthreads();
    for (int s = 64; s > 0; s >>= 1) {
        if (tid < s) red[tid] += red[tid + s];
        __syncthreads();
    }
    if (tid == 0) g_partial[blockIdx.x] = red[0];

    if (tid < 32) {
        out_idx[tok0 + tid] = (float)idxs[tid];
        atomicAdd(&out_bin[idxs[tid]], 1.0f);
    }
}

// ---------------- K4: deterministic loss finalize ----------------
__global__ void k4_loss(float* __restrict__ out_loss) {
    int lane = threadIdx.x;
    float s = 0.f;
    for (int i = lane * 32; i < lane * 32 + 32; ++i) s += g_partial[i];
#pragma unroll
    for (int off = 16; off > 0; off >>= 1)
        s += __shfl_xor_sync(0xffffffffu, s, off);
    if (lane == 0) {
        float m = s / 2097152.0f;
        out_loss[0] = 0.25f * m + m;
    }
}

extern "C" void kernel_launch(void* const* d_in, const int* in_sizes, int n_in,
                              void* d_out, int out_size) {
    const float* z  = (const float*)d_in[0];
    const float* ew = (const float*)d_in[1];
    float* out      = (float*)d_out;

    float* out_zq   = out;
    float* out_loss = out + OFF_LOSS;
    float* out_idx  = out + OFF_IDX;
    float* out_bin  = out + OFF_BIN;

    cudaMemsetAsync(out_bin, 0, NUM_EMBED * sizeof(float));

    k1_normalize<<<NUM_EMBED / 256, 256>>>(ew);

    cudaFuncSetAttribute(k2_all, cudaFuncAttributeMaxDynamicSharedMemorySize, SM_TOT);
    k2_all<<<NBLK, 128, SM_TOT>>>(z, ew, out_zq, out_idx, out_bin);

    k4_loss<<<1, 32>>>(out_loss);
}